// round 8
// baseline (speedup 1.0000x reference)
#include <cuda_runtime.h>
#include <math.h>

typedef unsigned long long ull;

// ---------------------------------------------------------------------------
// f32x2 packed-math helpers (sm_103a FFMA2 — only reachable via PTX)
// ---------------------------------------------------------------------------
__device__ __forceinline__ ull pack2(float x, float y) {
    ull r;
    asm("mov.b64 %0, {%1, %2};" : "=l"(r)
        : "r"(__float_as_uint(x)), "r"(__float_as_uint(y)));
    return r;
}
__device__ __forceinline__ float2 unpack2(ull v) {
    unsigned lo, hi;
    asm("mov.b64 {%0, %1}, %2;" : "=r"(lo), "=r"(hi) : "l"(v));
    return make_float2(__uint_as_float(lo), __uint_as_float(hi));
}
__device__ __forceinline__ void ffma2(ull& d, ull a, ull b) {
    asm("fma.rn.f32x2 %0, %1, %2, %0;" : "+l"(d) : "l"(a), "l"(b));
}

// ---------------------------------------------------------------------------
// Batched heterogeneous 64x64-tile SGEMM.
// Per z: C = (A [- A2]) @ B (+bias) * scale
// A: MxK row-major (lda; lda=0 broadcasts one row), B: KxN row-major (ldb),
// C: MxN (ldc). Requires M%64==0, N%64==0, K%16==0.
// grid = (maxN/64, maxM/64, nDescs); out-of-range tiles exit early.
// ---------------------------------------------------------------------------
struct GDesc {
    const float *A, *A2, *B, *bias;
    float *C;
    int M, N, K, lda, ldb, ldc;
    float scale;
};
struct GBatch { GDesc d[10]; };

__global__ __launch_bounds__(256) void sgemm64b(GBatch batch)
{
    const GDesc g = batch.d[blockIdx.z];
    const int m0 = blockIdx.y * 64, n0 = blockIdx.x * 64;
    if (m0 >= g.M || n0 >= g.N) return;

    __shared__ float As[16][64];   // [k][m]
    __shared__ float Bs[16][64];   // [k][n]
    const int t = threadIdx.x;

    const int ar = t >> 2,  ac = (t & 3)  << 2;   // A loader: 64 rows x 16 cols
    const int br = t >> 4,  bc = (t & 15) << 2;   // B loader: 16 rows x 64 cols
    const int tn = t >> 4,  tk = t & 15;          // 4x4 micro-tile

    ull acc[4][2];
#pragma unroll
    for (int i = 0; i < 4; i++) { acc[i][0] = 0ull; acc[i][1] = 0ull; }

    const float* Ap  = g.A + (size_t)(m0 + ar) * g.lda + ac;
    const float* A2p = g.A2 ? (g.A2 + (size_t)(m0 + ar) * g.lda + ac) : nullptr;
    const float* Bp  = g.B + (size_t)br * g.ldb + n0 + bc;

    for (int k0 = 0; k0 < g.K; k0 += 16) {
        float4 av = *(const float4*)(Ap + k0);
        if (A2p) {
            float4 a2 = *(const float4*)(A2p + k0);
            av.x -= a2.x; av.y -= a2.y; av.z -= a2.z; av.w -= a2.w;
        }
        As[ac + 0][ar] = av.x; As[ac + 1][ar] = av.y;
        As[ac + 2][ar] = av.z; As[ac + 3][ar] = av.w;
        *(float4*)&Bs[br][bc] = *(const float4*)(Bp + (size_t)k0 * g.ldb);
        __syncthreads();
#pragma unroll
        for (int kk = 0; kk < 16; kk++) {
            float4     a = *(const float4*)&As[kk][tn << 2];
            ulonglong2 b = *(const ulonglong2*)&Bs[kk][tk << 2];
            ull a0 = pack2(a.x, a.x), a1 = pack2(a.y, a.y);
            ull a2 = pack2(a.z, a.z), a3 = pack2(a.w, a.w);
            ffma2(acc[0][0], a0, b.x); ffma2(acc[0][1], a0, b.y);
            ffma2(acc[1][0], a1, b.x); ffma2(acc[1][1], a1, b.y);
            ffma2(acc[2][0], a2, b.x); ffma2(acc[2][1], a2, b.y);
            ffma2(acc[3][0], a3, b.x); ffma2(acc[3][1], a3, b.y);
        }
        __syncthreads();
    }

    float bb[4] = {0.f, 0.f, 0.f, 0.f};
    if (g.bias) {
#pragma unroll
        for (int j = 0; j < 4; j++) bb[j] = g.bias[n0 + (tk << 2) + j];
    }
#pragma unroll
    for (int i = 0; i < 4; i++) {
        float2 p0 = unpack2(acc[i][0]), p1 = unpack2(acc[i][1]);
        float4 o = make_float4((p0.x + bb[0]) * g.scale, (p0.y + bb[1]) * g.scale,
                               (p1.x + bb[2]) * g.scale, (p1.y + bb[3]) * g.scale);
        *(float4*)&g.C[(size_t)(m0 + (tn << 2) + i) * g.ldc + n0 + (tk << 2)] = o;
    }
}

// ---------------------------------------------------------------------------
// w[m][n][h] = sigmoid( qh[n, h*96:(h+1)*96] . dk[m, h*96:(h+1)*96] )
// grid = (M/64, N/32, 8), 256 threads
// ---------------------------------------------------------------------------
__global__ __launch_bounds__(256) void logits_w_kernel(
    const float* __restrict__ qh, const float* __restrict__ dk,
    float* __restrict__ w)
{
    __shared__ float qhT[96 * 32];   // [d][n]
    __shared__ float dkT[96 * 64];   // [d][m]
    const int t  = threadIdx.x;
    const int m0 = blockIdx.x * 64, n0 = blockIdx.y * 32, h = blockIdx.z;

    for (int idx = t; idx < 32 * 96; idx += 256) {
        int n = idx / 96, d = idx - n * 96;
        qhT[d * 32 + n] = qh[(size_t)(n0 + n) * 768 + h * 96 + d];
    }
    for (int idx = t; idx < 64 * 96; idx += 256) {
        int m = idx / 96, d = idx - m * 96;
        dkT[d * 64 + m] = dk[(size_t)(m0 + m) * 768 + h * 96 + d];
    }
    __syncthreads();

    const int wid = t >> 5, l = t & 31;
    const int nb = wid << 2, mb = l << 1;   // 4 n-rows x 2 m-cols per thread
    ull acc[4] = {0ull, 0ull, 0ull, 0ull};
#pragma unroll 4
    for (int d = 0; d < 96; d++) {
        float4 a = *(const float4*)&qhT[d * 32 + nb];
        ull    b = *(const ull*)&dkT[d * 64 + mb];
        ffma2(acc[0], pack2(a.x, a.x), b);
        ffma2(acc[1], pack2(a.y, a.y), b);
        ffma2(acc[2], pack2(a.z, a.z), b);
        ffma2(acc[3], pack2(a.w, a.w), b);
    }
#pragma unroll
    for (int i = 0; i < 4; i++) {
        float2 p = unpack2(acc[i]);
        int ng = n0 + nb + i;
        w[((size_t)(m0 + mb)     * 256 + ng) * 8 + h] = 1.f / (1.f + __expf(-p.x));
        w[((size_t)(m0 + mb + 1) * 256 + ng) * 8 + h] = 1.f / (1.f + __expf(-p.y));
    }
}

// ---------------------------------------------------------------------------
// Fused per-(n,m) MLP:
//   h1 = relu(A1[m] + sum_h w[n,m,h]*B1[m,h])            (256)
//   h2 = relu(h1 @ W2 + b2)                               (64)
//   out[n,m] = 0.5*tanh(h2 . W3 + b3)
// grid = (256/64 n-tiles, 512 m), 256 threads, 142336 B dynamic smem
// ---------------------------------------------------------------------------
__global__ __launch_bounds__(256) void fused_main_kernel(
    const float* __restrict__ A1, const float* __restrict__ B1,
    const float* __restrict__ wgt, const float* __restrict__ W2,
    const float* __restrict__ b2, const float* __restrict__ W3,
    const float* __restrict__ b3, float* __restrict__ out)
{
    extern __shared__ float sm[];
    float* W2s = sm;            // 16384 : [j][k] 256x64
    float* h1T = sm + 16384;    // 16384 : [j][n] 256x64
    float* wS  = sm + 32768;    // 512   : [n][h]
    float* B1s = sm + 33280;    // 2048  : [j][h]
    float* A1s = sm + 35328;    // 256

    const int t = threadIdx.x;
    const int m = blockIdx.y, n0 = blockIdx.x * 64;

    for (int i = t; i < 4096; i += 256)
        *(float4*)&W2s[i << 2] = *(const float4*)&W2[i << 2];
    for (int i = t; i < 2048; i += 256) {
        int h = i >> 8, j = i & 255;
        B1s[(j << 3) + h] = B1[(size_t)m * 2048 + i];
    }
    A1s[t] = A1[(size_t)m * 256 + t];
    for (int i = t; i < 512; i += 256)
        wS[i] = wgt[((size_t)m * 256 + n0) * 8 + i];
    __syncthreads();

    // phase 1: h1T[j][n] = relu(A1[j] + sum_h w[n][h]*B1[j][h])
    {
        const int n = t & 63, jg = t >> 6;   // warp-uniform jg, lane-consecutive n
        float4 wa = *(const float4*)&wS[n << 3];
        float4 wb = *(const float4*)&wS[(n << 3) + 4];
        ull wp0 = pack2(wa.x, wa.y), wp1 = pack2(wa.z, wa.w);
        ull wp2 = pack2(wb.x, wb.y), wp3 = pack2(wb.z, wb.w);
#pragma unroll 4
        for (int jj = 0; jj < 64; jj++) {
            int j = (jg << 6) + jj;
            ulonglong2 bA = *(const ulonglong2*)&B1s[j << 3];
            ull a = pack2(A1s[j], 0.f);
            ffma2(a, wp0, bA.x); ffma2(a, wp1, bA.y);
            ulonglong2 bB = *(const ulonglong2*)&B1s[(j << 3) + 4];
            ffma2(a, wp2, bB.x); ffma2(a, wp3, bB.y);
            float2 p = unpack2(a);
            h1T[(j << 6) + n] = fmaxf(p.x + p.y, 0.f);
        }
    }
    __syncthreads();

    // phase 2: C(64n x 64k) = h1(64x256) @ W2(256x64), 4x4 micro-tile
    const int tn = t >> 4, tk = t & 15;
    ull acc2[4][2];
#pragma unroll
    for (int i = 0; i < 4; i++) { acc2[i][0] = 0ull; acc2[i][1] = 0ull; }
#pragma unroll 4
    for (int j = 0; j < 256; j++) {
        float4     a = *(const float4*)&h1T[(j << 6) + (tn << 2)];
        ulonglong2 b = *(const ulonglong2*)&W2s[(j << 6) + (tk << 2)];
        ull a0 = pack2(a.x, a.x), a1 = pack2(a.y, a.y);
        ull a2 = pack2(a.z, a.z), a3 = pack2(a.w, a.w);
        ffma2(acc2[0][0], a0, b.x); ffma2(acc2[0][1], a0, b.y);
        ffma2(acc2[1][0], a1, b.x); ffma2(acc2[1][1], a1, b.y);
        ffma2(acc2[2][0], a2, b.x); ffma2(acc2[2][1], a2, b.y);
        ffma2(acc2[3][0], a3, b.x); ffma2(acc2[3][1], a3, b.y);
    }

    // phase 3: bias+relu, dot with W3, reduce across the 16 tk-threads
    float b2v[4], w3v[4];
#pragma unroll
    for (int j = 0; j < 4; j++) {
        b2v[j] = b2[(tk << 2) + j];
        w3v[j] = W3[(tk << 2) + j];
    }
    const float b3v = b3[0];
#pragma unroll
    for (int i = 0; i < 4; i++) {
        float2 p0 = unpack2(acc2[i][0]), p1 = unpack2(acc2[i][1]);
        float s = fmaxf(p0.x + b2v[0], 0.f) * w3v[0]
                + fmaxf(p0.y + b2v[1], 0.f) * w3v[1]
                + fmaxf(p1.x + b2v[2], 0.f) * w3v[2]
                + fmaxf(p1.y + b2v[3], 0.f) * w3v[3];
        s += __shfl_xor_sync(0xffffffffu, s, 1);
        s += __shfl_xor_sync(0xffffffffu, s, 2);
        s += __shfl_xor_sync(0xffffffffu, s, 4);
        s += __shfl_xor_sync(0xffffffffu, s, 8);
        if (tk == 0)
            out[(size_t)(n0 + (tn << 2) + i) * 512 + m] = 0.5f * tanhf(s + b3v);
    }
}

// ---------------------------------------------------------------------------
// Scratch (single __device__ global; ~19.2 MB) — allocation-free.
// ---------------------------------------------------------------------------
__device__ float g_scr[4800768];

static const int OFF_Q    = 0;         // 256*768
static const int OFF_IMG  = 196608;    // 512*768
static const int OFF_TGT  = 589824;    // 512*768
static const int OFF_QH   = 983040;    // 256*768
static const int OFF_DK   = 1179648;   // 512*768
static const int OFF_DV   = 1572864;   // 512*768
static const int OFF_VT   = 1966080;   // 512*768
static const int OFF_M1   = 2359296;   // 768*256
static const int OFF_C1B  = 2555904;   // 64*256 (row 0 = c1)
static const int OFF_A1   = 2572288;   // 512*256
static const int OFF_B1   = 2703360;   // 512*8*256
static const int OFF_W    = 3751936;   // 512*256*8

static inline GDesc mk(const float* A, const float* A2, const float* B,
                       const float* bias, float* C, int M, int N, int K,
                       int lda, int ldb, int ldc, float scale)
{
    GDesc g; g.A = A; g.A2 = A2; g.B = B; g.bias = bias; g.C = C;
    g.M = M; g.N = N; g.K = K; g.lda = lda; g.ldb = ldb; g.ldc = ldc;
    g.scale = scale; return g;
}

extern "C" void kernel_launch(void* const* d_in, const int* in_sizes, int n_in,
                              void* d_out, int out_size)
{
    (void)in_sizes; (void)n_in; (void)out_size;
    const float* QE  = (const float*)d_in[0];
    const float* IE  = (const float*)d_in[1];
    const float* TE  = (const float*)d_in[2];
    const float* Wq  = (const float*)d_in[3];
    const float* bq  = (const float*)d_in[4];
    const float* Wi  = (const float*)d_in[5];
    const float* bi  = (const float*)d_in[6];
    const float* Wt  = (const float*)d_in[7];
    const float* bt  = (const float*)d_in[8];
    const float* Wiq = (const float*)d_in[9];
    const float* biq = (const float*)d_in[10];
    const float* Wik = (const float*)d_in[11];
    const float* Wiv = (const float*)d_in[13];
    const float* biv = (const float*)d_in[14];
    const float* Wo  = (const float*)d_in[15];
    const float* bo  = (const float*)d_in[16];
    const float* W1  = (const float*)d_in[17];
    const float* b1  = (const float*)d_in[18];
    const float* W2  = (const float*)d_in[19];
    const float* b2  = (const float*)d_in[20];
    const float* W3  = (const float*)d_in[21];
    const float* b3  = (const float*)d_in[22];
    // note: bik (d_in[12]) cancels in dk = (img - tgt) @ Wik

    float* scr = nullptr;
    cudaGetSymbolAddress((void**)&scr, g_scr);
    float *q   = scr + OFF_Q,   *img = scr + OFF_IMG, *tgt = scr + OFF_TGT;
    float *qh  = scr + OFF_QH,  *dk  = scr + OFF_DK,  *dv  = scr + OFF_DV;
    float *vt  = scr + OFF_VT,  *M1  = scr + OFF_M1,  *c1b = scr + OFF_C1B;
    float *A1  = scr + OFF_A1,  *B1  = scr + OFF_B1,  *w   = scr + OFF_W;

    const float scale = 1.0f / sqrtf(96.0f);

    // Stage 1 (depends only on inputs): input projections, M1 = Wo@W1,
    // c1 = bo@W1 + b1 (as a degenerate lda=0 row-broadcast GEMM, row 0 of c1b)
    {
        GBatch b;
        b.d[0] = mk(QE, nullptr, Wq, bq,      q,   256, 768, 768, 768, 768, 768, 1.f);
        b.d[1] = mk(IE, nullptr, Wi, bi,      img, 512, 768, 768, 768, 768, 768, 1.f);
        b.d[2] = mk(TE, nullptr, Wt, bt,      tgt, 512, 768, 768, 768, 768, 768, 1.f);
        b.d[3] = mk(Wo, nullptr, W1, nullptr, M1,  768, 256, 768, 768, 256, 256, 1.f);
        b.d[4] = mk(bo, nullptr, W1, b1,      c1b, 64,  256, 768, 0,   256, 256, 1.f);
        sgemm64b<<<dim3(12, 12, 5), 256>>>(b);
    }

    // Stage 2: MHA in-projections (k/v biases cancel in the img-tgt diffs)
    {
        GBatch b;
        b.d[0] = mk(q,   nullptr, Wiq, biq,     qh, 256, 768, 768, 768, 768, 768, scale);
        b.d[1] = mk(img, tgt,     Wik, nullptr, dk, 512, 768, 768, 768, 768, 768, 1.f);
        b.d[2] = mk(img, tgt,     Wiv, nullptr, dv, 512, 768, 768, 768, 768, 768, 1.f);
        b.d[3] = mk(tgt, nullptr, Wiv, biv,     vt, 512, 768, 768, 768, 768, 768, 1.f);
        sgemm64b<<<dim3(12, 8, 4), 256>>>(b);
    }

    // Stage 3: A1 = vt@M1 + c1 ; B1[m][h] = dv[m,h*96:]@M1[h*96:,:]
    {
        GBatch b;
        b.d[0] = mk(vt, nullptr, M1, c1b, A1, 512, 256, 768, 768, 256, 256, 1.f);
        for (int h = 0; h < 8; h++)
            b.d[1 + h] = mk(dv + h * 96, nullptr, M1 + h * 96 * 256, nullptr,
                            B1 + h * 256, 512, 256, 96, 768, 256, 2048, 1.f);
        sgemm64b<<<dim3(4, 8, 9), 256>>>(b);
    }

    // attention weights
    logits_w_kernel<<<dim3(8, 8, 8), 256>>>(qh, dk, w);

    // fused MLP + output
    cudaFuncSetAttribute(fused_main_kernel,
                         cudaFuncAttributeMaxDynamicSharedMemorySize, 142336);
    fused_main_kernel<<<dim3(4, 512), 256, 142336>>>(A1, B1, w, W2, b2, W3, b3,
                                                     (float*)d_out);
}

// round 9
// speedup vs baseline: 1.0447x; 1.0447x over previous
#include <cuda_runtime.h>
#include <math.h>

typedef unsigned long long ull;

// ---------------------------------------------------------------------------
// f32x2 packed-math helpers (sm_103a FFMA2 — only reachable via PTX)
// ---------------------------------------------------------------------------
__device__ __forceinline__ ull pack2(float x, float y) {
    ull r;
    asm("mov.b64 %0, {%1, %2};" : "=l"(r)
        : "r"(__float_as_uint(x)), "r"(__float_as_uint(y)));
    return r;
}
__device__ __forceinline__ float2 unpack2(ull v) {
    unsigned lo, hi;
    asm("mov.b64 {%0, %1}, %2;" : "=r"(lo), "=r"(hi) : "l"(v));
    return make_float2(__uint_as_float(lo), __uint_as_float(hi));
}
__device__ __forceinline__ void ffma2(ull& d, ull a, ull b) {
    asm("fma.rn.f32x2 %0, %1, %2, %0;" : "+l"(d) : "l"(a), "l"(b));
}

// ---------------------------------------------------------------------------
// Batched heterogeneous 64x64-tile SGEMM, double-buffered k-loop.
// Per z: C = (A [- A2]) @ B (+bias) * scale
// A: MxK row-major (lda; lda=0 broadcasts one row), B: KxN row-major (ldb),
// C: MxN (ldc). Requires M%64==0, N%64==0, K%16==0.
// grid = (maxN/64, maxM/64, nDescs); out-of-range tiles exit early.
// ---------------------------------------------------------------------------
struct GDesc {
    const float *A, *A2, *B, *bias;
    float *C;
    int M, N, K, lda, ldb, ldc;
    float scale;
};
struct GBatch { GDesc d[10]; };

__global__ __launch_bounds__(256) void sgemm64b(GBatch batch)
{
    const GDesc g = batch.d[blockIdx.z];
    const int m0 = blockIdx.y * 64, n0 = blockIdx.x * 64;
    if (m0 >= g.M || n0 >= g.N) return;

    __shared__ float As[2][16][64];   // [buf][k][m]
    __shared__ float Bs[2][16][64];   // [buf][k][n]
    const int t = threadIdx.x;

    const int ar = t >> 2,  ac = (t & 3)  << 2;   // A loader: 64 rows x 16 cols
    const int br = t >> 4,  bc = (t & 15) << 2;   // B loader: 16 rows x 64 cols
    const int tn = t >> 4,  tk = t & 15;          // 4x4 micro-tile

    ull acc[4][2];
#pragma unroll
    for (int i = 0; i < 4; i++) { acc[i][0] = 0ull; acc[i][1] = 0ull; }

    const float* Ap  = g.A + (size_t)(m0 + ar) * g.lda + ac;
    const float* A2p = g.A2 ? (g.A2 + (size_t)(m0 + ar) * g.lda + ac) : nullptr;
    const float* Bp  = g.B + (size_t)br * g.ldb + n0 + bc;

    const int nT = g.K >> 4;

    // prologue: tile 0 -> buffer 0
    float4 av = *(const float4*)(Ap);
    if (A2p) {
        float4 a2 = *(const float4*)(A2p);
        av.x -= a2.x; av.y -= a2.y; av.z -= a2.z; av.w -= a2.w;
    }
    float4 bv = *(const float4*)(Bp);
    As[0][ac + 0][ar] = av.x; As[0][ac + 1][ar] = av.y;
    As[0][ac + 2][ar] = av.z; As[0][ac + 3][ar] = av.w;
    *(float4*)&Bs[0][br][bc] = bv;
    __syncthreads();

    for (int tt = 0; tt < nT; tt++) {
        const int p = tt & 1;
        const bool more = (tt + 1 < nT);
        if (more) {   // issue next tile's global loads before computing
            const int k0 = (tt + 1) << 4;
            av = *(const float4*)(Ap + k0);
            if (A2p) {
                float4 a2 = *(const float4*)(A2p + k0);
                av.x -= a2.x; av.y -= a2.y; av.z -= a2.z; av.w -= a2.w;
            }
            bv = *(const float4*)(Bp + (size_t)k0 * g.ldb);
        }
#pragma unroll
        for (int kk = 0; kk < 16; kk++) {
            float4     a = *(const float4*)&As[p][kk][tn << 2];
            ulonglong2 b = *(const ulonglong2*)&Bs[p][kk][tk << 2];
            ull a0 = pack2(a.x, a.x), a1 = pack2(a.y, a.y);
            ull a2 = pack2(a.z, a.z), a3 = pack2(a.w, a.w);
            ffma2(acc[0][0], a0, b.x); ffma2(acc[0][1], a0, b.y);
            ffma2(acc[1][0], a1, b.x); ffma2(acc[1][1], a1, b.y);
            ffma2(acc[2][0], a2, b.x); ffma2(acc[2][1], a2, b.y);
            ffma2(acc[3][0], a3, b.x); ffma2(acc[3][1], a3, b.y);
        }
        if (more) {   // safe: buffer p^1 was last read in iter tt-1, sync passed
            const int q = p ^ 1;
            As[q][ac + 0][ar] = av.x; As[q][ac + 1][ar] = av.y;
            As[q][ac + 2][ar] = av.z; As[q][ac + 3][ar] = av.w;
            *(float4*)&Bs[q][br][bc] = bv;
        }
        __syncthreads();
    }

    float bb[4] = {0.f, 0.f, 0.f, 0.f};
    if (g.bias) {
#pragma unroll
        for (int j = 0; j < 4; j++) bb[j] = g.bias[n0 + (tk << 2) + j];
    }
#pragma unroll
    for (int i = 0; i < 4; i++) {
        float2 p0 = unpack2(acc[i][0]), p1 = unpack2(acc[i][1]);
        float4 o = make_float4((p0.x + bb[0]) * g.scale, (p0.y + bb[1]) * g.scale,
                               (p1.x + bb[2]) * g.scale, (p1.y + bb[3]) * g.scale);
        *(float4*)&g.C[(size_t)(m0 + (tn << 2) + i) * g.ldc + n0 + (tk << 2)] = o;
    }
}

// ---------------------------------------------------------------------------
// w[m][n][h] = sigmoid( qh[n, h*96:(h+1)*96] . dk[m, h*96:(h+1)*96] )
// 64n x 64m tiles, 4x4 micro-tile. grid = (M/64, N/64, 8), 256 threads.
// ---------------------------------------------------------------------------
__global__ __launch_bounds__(256) void logits_w_kernel(
    const float* __restrict__ qh, const float* __restrict__ dk,
    float* __restrict__ w)
{
    __shared__ float qhT[96 * 64];   // [d][n]  24KB
    __shared__ float dkT[96 * 64];   // [d][m]  24KB
    const int t  = threadIdx.x;
    const int m0 = blockIdx.x * 64, n0 = blockIdx.y * 64, h = blockIdx.z;

    // staging: consecutive threads take consecutive rows -> conflict-free STS
    for (int idx = t; idx < 1536; idx += 256) {
        const int c = idx >> 6, r = idx & 63;        // c: float4 group along d
        float4 v = *(const float4*)&qh[(size_t)(n0 + r) * 768 + h * 96 + (c << 2)];
        qhT[((c << 2) + 0) * 64 + r] = v.x;
        qhT[((c << 2) + 1) * 64 + r] = v.y;
        qhT[((c << 2) + 2) * 64 + r] = v.z;
        qhT[((c << 2) + 3) * 64 + r] = v.w;
    }
    for (int idx = t; idx < 1536; idx += 256) {
        const int c = idx >> 6, r = idx & 63;
        float4 v = *(const float4*)&dk[(size_t)(m0 + r) * 768 + h * 96 + (c << 2)];
        dkT[((c << 2) + 0) * 64 + r] = v.x;
        dkT[((c << 2) + 1) * 64 + r] = v.y;
        dkT[((c << 2) + 2) * 64 + r] = v.z;
        dkT[((c << 2) + 3) * 64 + r] = v.w;
    }
    __syncthreads();

    const int tn = t >> 4, tm = t & 15;   // 4 n-rows x 4 m-cols per thread
    ull acc[4][2];
#pragma unroll
    for (int i = 0; i < 4; i++) { acc[i][0] = 0ull; acc[i][1] = 0ull; }

#pragma unroll 4
    for (int d = 0; d < 96; d++) {
        float4     a = *(const float4*)&qhT[d * 64 + (tn << 2)];
        ulonglong2 b = *(const ulonglong2*)&dkT[d * 64 + (tm << 2)];
        ull a0 = pack2(a.x, a.x), a1 = pack2(a.y, a.y);
        ull a2 = pack2(a.z, a.z), a3 = pack2(a.w, a.w);
        ffma2(acc[0][0], a0, b.x); ffma2(acc[0][1], a0, b.y);
        ffma2(acc[1][0], a1, b.x); ffma2(acc[1][1], a1, b.y);
        ffma2(acc[2][0], a2, b.x); ffma2(acc[2][1], a2, b.y);
        ffma2(acc[3][0], a3, b.x); ffma2(acc[3][1], a3, b.y);
    }

#pragma unroll
    for (int i = 0; i < 4; i++) {
        float2 p0 = unpack2(acc[i][0]), p1 = unpack2(acc[i][1]);
        const int ng = n0 + (tn << 2) + i;
        const size_t mg = (size_t)(m0 + (tm << 2));
        w[(mg + 0) * 2048 + ng * 8 + h] = 1.f / (1.f + __expf(-p0.x));
        w[(mg + 1) * 2048 + ng * 8 + h] = 1.f / (1.f + __expf(-p0.y));
        w[(mg + 2) * 2048 + ng * 8 + h] = 1.f / (1.f + __expf(-p1.x));
        w[(mg + 3) * 2048 + ng * 8 + h] = 1.f / (1.f + __expf(-p1.y));
    }
}

// ---------------------------------------------------------------------------
// Fused per-(n,m) MLP:
//   h1 = relu(A1[m] + sum_h w[n,m,h]*B1[m,h])            (256)
//   h2 = relu(h1 @ W2 + b2)                               (64)
//   out[n,m] = 0.5*tanh(h2 . W3 + b3)
// grid = (256/64 n-tiles, 512 m), 256 threads, 142336 B dynamic smem
// ---------------------------------------------------------------------------
__global__ __launch_bounds__(256) void fused_main_kernel(
    const float* __restrict__ A1, const float* __restrict__ B1,
    const float* __restrict__ wgt, const float* __restrict__ W2,
    const float* __restrict__ b2, const float* __restrict__ W3,
    const float* __restrict__ b3, float* __restrict__ out)
{
    extern __shared__ float sm[];
    float* W2s = sm;            // 16384 : [j][k] 256x64
    float* h1T = sm + 16384;    // 16384 : [j][n] 256x64
    float* wS  = sm + 32768;    // 512   : [n][h]
    float* B1s = sm + 33280;    // 2048  : [j][h]
    float* A1s = sm + 35328;    // 256

    const int t = threadIdx.x;
    const int m = blockIdx.y, n0 = blockIdx.x * 64;

    for (int i = t; i < 4096; i += 256)
        *(float4*)&W2s[i << 2] = *(const float4*)&W2[i << 2];
    for (int i = t; i < 2048; i += 256) {
        int h = i >> 8, j = i & 255;
        B1s[(j << 3) + h] = B1[(size_t)m * 2048 + i];
    }
    A1s[t] = A1[(size_t)m * 256 + t];
    for (int i = t; i < 512; i += 256)
        wS[i] = wgt[((size_t)m * 256 + n0) * 8 + i];
    __syncthreads();

    // phase 1: h1T[j][n] = relu(A1[j] + sum_h w[n][h]*B1[j][h])
    {
        const int n = t & 63, jg = t >> 6;   // warp-uniform jg, lane-consecutive n
        float4 wa = *(const float4*)&wS[n << 3];
        float4 wb = *(const float4*)&wS[(n << 3) + 4];
        ull wp0 = pack2(wa.x, wa.y), wp1 = pack2(wa.z, wa.w);
        ull wp2 = pack2(wb.x, wb.y), wp3 = pack2(wb.z, wb.w);
#pragma unroll 4
        for (int jj = 0; jj < 64; jj++) {
            int j = (jg << 6) + jj;
            ulonglong2 bA = *(const ulonglong2*)&B1s[j << 3];
            ull a = pack2(A1s[j], 0.f);
            ffma2(a, wp0, bA.x); ffma2(a, wp1, bA.y);
            ulonglong2 bB = *(const ulonglong2*)&B1s[(j << 3) + 4];
            ffma2(a, wp2, bB.x); ffma2(a, wp3, bB.y);
            float2 p = unpack2(a);
            h1T[(j << 6) + n] = fmaxf(p.x + p.y, 0.f);
        }
    }
    __syncthreads();

    // phase 2: C(64n x 64k) = h1(64x256) @ W2(256x64), 4x4 micro-tile
    const int tn = t >> 4, tk = t & 15;
    ull acc2[4][2];
#pragma unroll
    for (int i = 0; i < 4; i++) { acc2[i][0] = 0ull; acc2[i][1] = 0ull; }
#pragma unroll 4
    for (int j = 0; j < 256; j++) {
        float4     a = *(const float4*)&h1T[(j << 6) + (tn << 2)];
        ulonglong2 b = *(const ulonglong2*)&W2s[(j << 6) + (tk << 2)];
        ull a0 = pack2(a.x, a.x), a1 = pack2(a.y, a.y);
        ull a2 = pack2(a.z, a.z), a3 = pack2(a.w, a.w);
        ffma2(acc2[0][0], a0, b.x); ffma2(acc2[0][1], a0, b.y);
        ffma2(acc2[1][0], a1, b.x); ffma2(acc2[1][1], a1, b.y);
        ffma2(acc2[2][0], a2, b.x); ffma2(acc2[2][1], a2, b.y);
        ffma2(acc2[3][0], a3, b.x); ffma2(acc2[3][1], a3, b.y);
    }

    // phase 3: bias+relu, dot with W3, reduce across the 16 tk-threads
    float b2v[4], w3v[4];
#pragma unroll
    for (int j = 0; j < 4; j++) {
        b2v[j] = b2[(tk << 2) + j];
        w3v[j] = W3[(tk << 2) + j];
    }
    const float b3v = b3[0];
#pragma unroll
    for (int i = 0; i < 4; i++) {
        float2 p0 = unpack2(acc2[i][0]), p1 = unpack2(acc2[i][1]);
        float s = fmaxf(p0.x + b2v[0], 0.f) * w3v[0]
                + fmaxf(p0.y + b2v[1], 0.f) * w3v[1]
                + fmaxf(p1.x + b2v[2], 0.f) * w3v[2]
                + fmaxf(p1.y + b2v[3], 0.f) * w3v[3];
        s += __shfl_xor_sync(0xffffffffu, s, 1);
        s += __shfl_xor_sync(0xffffffffu, s, 2);
        s += __shfl_xor_sync(0xffffffffu, s, 4);
        s += __shfl_xor_sync(0xffffffffu, s, 8);
        if (tk == 0)
            out[(size_t)(n0 + (tn << 2) + i) * 512 + m] = 0.5f * tanhf(s + b3v);
    }
}

// ---------------------------------------------------------------------------
// Scratch (single __device__ global; ~19.2 MB) — allocation-free.
// ---------------------------------------------------------------------------
__device__ float g_scr[4800768];

static const int OFF_Q    = 0;         // 256*768
static const int OFF_IMG  = 196608;    // 512*768
static const int OFF_TGT  = 589824;    // 512*768
static const int OFF_QH   = 983040;    // 256*768
static const int OFF_DK   = 1179648;   // 512*768
static const int OFF_DV   = 1572864;   // 512*768
static const int OFF_VT   = 1966080;   // 512*768
static const int OFF_M1   = 2359296;   // 768*256
static const int OFF_C1B  = 2555904;   // 64*256 (row 0 = c1)
static const int OFF_A1   = 2572288;   // 512*256
static const int OFF_B1   = 2703360;   // 512*8*256
static const int OFF_W    = 3751936;   // 512*256*8

static inline GDesc mk(const float* A, const float* A2, const float* B,
                       const float* bias, float* C, int M, int N, int K,
                       int lda, int ldb, int ldc, float scale)
{
    GDesc g; g.A = A; g.A2 = A2; g.B = B; g.bias = bias; g.C = C;
    g.M = M; g.N = N; g.K = K; g.lda = lda; g.ldb = ldb; g.ldc = ldc;
    g.scale = scale; return g;
}

extern "C" void kernel_launch(void* const* d_in, const int* in_sizes, int n_in,
                              void* d_out, int out_size)
{
    (void)in_sizes; (void)n_in; (void)out_size;
    const float* QE  = (const float*)d_in[0];
    const float* IE  = (const float*)d_in[1];
    const float* TE  = (const float*)d_in[2];
    const float* Wq  = (const float*)d_in[3];
    const float* bq  = (const float*)d_in[4];
    const float* Wi  = (const float*)d_in[5];
    const float* bi  = (const float*)d_in[6];
    const float* Wt  = (const float*)d_in[7];
    const float* bt  = (const float*)d_in[8];
    const float* Wiq = (const float*)d_in[9];
    const float* biq = (const float*)d_in[10];
    const float* Wik = (const float*)d_in[11];
    const float* Wiv = (const float*)d_in[13];
    const float* biv = (const float*)d_in[14];
    const float* Wo  = (const float*)d_in[15];
    const float* bo  = (const float*)d_in[16];
    const float* W1  = (const float*)d_in[17];
    const float* b1  = (const float*)d_in[18];
    const float* W2  = (const float*)d_in[19];
    const float* b2  = (const float*)d_in[20];
    const float* W3  = (const float*)d_in[21];
    const float* b3  = (const float*)d_in[22];
    // note: bik (d_in[12]) cancels in dk = (img - tgt) @ Wik

    float* scr = nullptr;
    cudaGetSymbolAddress((void**)&scr, g_scr);
    float *q   = scr + OFF_Q,   *img = scr + OFF_IMG, *tgt = scr + OFF_TGT;
    float *qh  = scr + OFF_QH,  *dk  = scr + OFF_DK,  *dv  = scr + OFF_DV;
    float *vt  = scr + OFF_VT,  *M1  = scr + OFF_M1,  *c1b = scr + OFF_C1B;
    float *A1  = scr + OFF_A1,  *B1  = scr + OFF_B1,  *w   = scr + OFF_W;

    const float scale = 1.0f / sqrtf(96.0f);

    // Stage 1 (depends only on inputs): input projections, M1 = Wo@W1,
    // c1 = bo@W1 + b1 (as a degenerate lda=0 row-broadcast GEMM, row 0 of c1b)
    {
        GBatch b;
        b.d[0] = mk(QE, nullptr, Wq, bq,      q,   256, 768, 768, 768, 768, 768, 1.f);
        b.d[1] = mk(IE, nullptr, Wi, bi,      img, 512, 768, 768, 768, 768, 768, 1.f);
        b.d[2] = mk(TE, nullptr, Wt, bt,      tgt, 512, 768, 768, 768, 768, 768, 1.f);
        b.d[3] = mk(Wo, nullptr, W1, nullptr, M1,  768, 256, 768, 768, 256, 256, 1.f);
        b.d[4] = mk(bo, nullptr, W1, b1,      c1b, 64,  256, 768, 0,   256, 256, 1.f);
        sgemm64b<<<dim3(12, 12, 5), 256>>>(b);
    }

    // Stage 2: MHA in-projections (k/v biases cancel in the img-tgt diffs)
    {
        GBatch b;
        b.d[0] = mk(q,   nullptr, Wiq, biq,     qh, 256, 768, 768, 768, 768, 768, scale);
        b.d[1] = mk(img, tgt,     Wik, nullptr, dk, 512, 768, 768, 768, 768, 768, 1.f);
        b.d[2] = mk(img, tgt,     Wiv, nullptr, dv, 512, 768, 768, 768, 768, 768, 1.f);
        b.d[3] = mk(tgt, nullptr, Wiv, biv,     vt, 512, 768, 768, 768, 768, 768, 1.f);
        sgemm64b<<<dim3(12, 8, 4), 256>>>(b);
    }

    // Stage 3: A1 = vt@M1 + c1 ; B1[m][h] = dv[m,h*96:]@M1[h*96:,:]
    {
        GBatch b;
        b.d[0] = mk(vt, nullptr, M1, c1b, A1, 512, 256, 768, 768, 256, 256, 1.f);
        for (int h = 0; h < 8; h++)
            b.d[1 + h] = mk(dv + h * 96, nullptr, M1 + h * 96 * 256, nullptr,
                            B1 + h * 256, 512, 256, 96, 768, 256, 2048, 1.f);
        sgemm64b<<<dim3(4, 8, 9), 256>>>(b);
    }

    // attention weights (64x64 tiles per head)
    logits_w_kernel<<<dim3(8, 4, 8), 256>>>(qh, dk, w);

    // fused MLP + output
    cudaFuncSetAttribute(fused_main_kernel,
                         cudaFuncAttributeMaxDynamicSharedMemorySize, 142336);
    fused_main_kernel<<<dim3(4, 512), 256, 142336>>>(A1, B1, w, W2, b2, W3, b3,
                                                     (float*)d_out);
}

// round 14
// speedup vs baseline: 1.2254x; 1.1729x over previous
#include <cuda_runtime.h>
#include <math.h>

typedef unsigned long long ull;

// ---------------------------------------------------------------------------
// f32x2 packed-math helpers (sm_103a FFMA2 — only reachable via PTX)
// ---------------------------------------------------------------------------
__device__ __forceinline__ ull pack2(float x, float y) {
    ull r;
    asm("mov.b64 %0, {%1, %2};" : "=l"(r)
        : "r"(__float_as_uint(x)), "r"(__float_as_uint(y)));
    return r;
}
__device__ __forceinline__ float2 unpack2(ull v) {
    unsigned lo, hi;
    asm("mov.b64 {%0, %1}, %2;" : "=r"(lo), "=r"(hi) : "l"(v));
    return make_float2(__uint_as_float(lo), __uint_as_float(hi));
}
__device__ __forceinline__ void ffma2(ull& d, ull a, ull b) {
    asm("fma.rn.f32x2 %0, %1, %2, %0;" : "+l"(d) : "l"(a), "l"(b));
}

// ---------------------------------------------------------------------------
// Batched heterogeneous 64x64-tile SGEMM, double-buffered k-loop.
// Per z: C = (A [- A2]) @ B (+bias) * scale
// ---------------------------------------------------------------------------
struct GDesc {
    const float *A, *A2, *B, *bias;
    float *C;
    int M, N, K, lda, ldb, ldc;
    float scale;
};
struct GBatch { GDesc d[10]; };

__global__ __launch_bounds__(256) void sgemm64b(GBatch batch)
{
    const GDesc g = batch.d[blockIdx.z];
    const int m0 = blockIdx.y * 64, n0 = blockIdx.x * 64;
    if (m0 >= g.M || n0 >= g.N) return;

    __shared__ float As[2][16][64];   // [buf][k][m]
    __shared__ float Bs[2][16][64];   // [buf][k][n]
    const int t = threadIdx.x;

    const int ar = t >> 2,  ac = (t & 3)  << 2;
    const int br = t >> 4,  bc = (t & 15) << 2;
    const int tn = t >> 4,  tk = t & 15;

    ull acc[4][2];
#pragma unroll
    for (int i = 0; i < 4; i++) { acc[i][0] = 0ull; acc[i][1] = 0ull; }

    const float* Ap  = g.A + (size_t)(m0 + ar) * g.lda + ac;
    const float* A2p = g.A2 ? (g.A2 + (size_t)(m0 + ar) * g.lda + ac) : nullptr;
    const float* Bp  = g.B + (size_t)br * g.ldb + n0 + bc;

    const int nT = g.K >> 4;

    float4 av = *(const float4*)(Ap);
    if (A2p) {
        float4 a2 = *(const float4*)(A2p);
        av.x -= a2.x; av.y -= a2.y; av.z -= a2.z; av.w -= a2.w;
    }
    float4 bv = *(const float4*)(Bp);
    As[0][ac + 0][ar] = av.x; As[0][ac + 1][ar] = av.y;
    As[0][ac + 2][ar] = av.z; As[0][ac + 3][ar] = av.w;
    *(float4*)&Bs[0][br][bc] = bv;
    __syncthreads();

    for (int tt = 0; tt < nT; tt++) {
        const int p = tt & 1;
        const bool more = (tt + 1 < nT);
        if (more) {
            const int k0 = (tt + 1) << 4;
            av = *(const float4*)(Ap + k0);
            if (A2p) {
                float4 a2 = *(const float4*)(A2p + k0);
                av.x -= a2.x; av.y -= a2.y; av.z -= a2.z; av.w -= a2.w;
            }
            bv = *(const float4*)(Bp + (size_t)k0 * g.ldb);
        }
#pragma unroll
        for (int kk = 0; kk < 16; kk++) {
            float4     a = *(const float4*)&As[p][kk][tn << 2];
            ulonglong2 b = *(const ulonglong2*)&Bs[p][kk][tk << 2];
            ull a0 = pack2(a.x, a.x), a1 = pack2(a.y, a.y);
            ull a2 = pack2(a.z, a.z), a3 = pack2(a.w, a.w);
            ffma2(acc[0][0], a0, b.x); ffma2(acc[0][1], a0, b.y);
            ffma2(acc[1][0], a1, b.x); ffma2(acc[1][1], a1, b.y);
            ffma2(acc[2][0], a2, b.x); ffma2(acc[2][1], a2, b.y);
            ffma2(acc[3][0], a3, b.x); ffma2(acc[3][1], a3, b.y);
        }
        if (more) {
            const int q = p ^ 1;
            As[q][ac + 0][ar] = av.x; As[q][ac + 1][ar] = av.y;
            As[q][ac + 2][ar] = av.z; As[q][ac + 3][ar] = av.w;
            *(float4*)&Bs[q][br][bc] = bv;
        }
        __syncthreads();
    }

    float bb[4] = {0.f, 0.f, 0.f, 0.f};
    if (g.bias) {
#pragma unroll
        for (int j = 0; j < 4; j++) bb[j] = g.bias[n0 + (tk << 2) + j];
    }
#pragma unroll
    for (int i = 0; i < 4; i++) {
        float2 p0 = unpack2(acc[i][0]), p1 = unpack2(acc[i][1]);
        float4 o = make_float4((p0.x + bb[0]) * g.scale, (p0.y + bb[1]) * g.scale,
                               (p1.x + bb[2]) * g.scale, (p1.y + bb[3]) * g.scale);
        *(float4*)&g.C[(size_t)(m0 + (tn << 2) + i) * g.ldc + n0 + (tk << 2)] = o;
    }
}

// ---------------------------------------------------------------------------
// w[m][n][h] = sigmoid( qh[n,h*96:] . dk[m,h*96:] )
// 64n x 64m tiles. grid = (M/64, N/64, 8), 256 threads.
// Staging: coalesced row loads + XOR-swizzled [d][row] smem
//   idx(d, r) = d*64 + (r ^ (((d>>2)&7)<<2))   -- float4-alignment preserved
// ---------------------------------------------------------------------------
__global__ __launch_bounds__(256) void logits_w_kernel(
    const float* __restrict__ qh, const float* __restrict__ dk,
    float* __restrict__ w)
{
    __shared__ float qhT[96 * 64];   // 24KB, swizzled [d][n]
    __shared__ float dkT[96 * 64];   // 24KB, swizzled [d][m]
    const int t  = threadIdx.x;
    const int wid = t >> 5, lane = t & 31;
    const int m0 = blockIdx.x * 64, n0 = blockIdx.y * 64, h = blockIdx.z;

    // lanes 0-23 of each warp load one row's 96 floats (coalesced, nL~4)
    if (lane < 24) {
        const int c = lane, s = (c & 7) << 2, base = (c << 2) * 64;
#pragma unroll
        for (int i = 0; i < 8; i++) {
            const int r = (i << 3) + wid;
            float4 v = *(const float4*)&qh[(size_t)(n0 + r) * 768 + h * 96 + (c << 2)];
            const int rx = r ^ s;
            qhT[base + rx] = v.x;       qhT[base + 64 + rx] = v.y;
            qhT[base + 128 + rx] = v.z; qhT[base + 192 + rx] = v.w;
        }
#pragma unroll
        for (int i = 0; i < 8; i++) {
            const int r = (i << 3) + wid;
            float4 v = *(const float4*)&dk[(size_t)(m0 + r) * 768 + h * 96 + (c << 2)];
            const int rx = r ^ s;
            dkT[base + rx] = v.x;       dkT[base + 64 + rx] = v.y;
            dkT[base + 128 + rx] = v.z; dkT[base + 192 + rx] = v.w;
        }
    }
    __syncthreads();

    const int tn = t >> 4, tm = t & 15;   // 4 n-rows x 4 m-cols per thread
    ull acc[4][2];
#pragma unroll
    for (int i = 0; i < 4; i++) { acc[i][0] = 0ull; acc[i][1] = 0ull; }

#pragma unroll 4
    for (int d = 0; d < 96; d++) {
        const int s = ((d >> 2) & 7) << 2;
        float4     a = *(const float4*)&qhT[d * 64 + ((tn << 2) ^ s)];
        ulonglong2 b = *(const ulonglong2*)&dkT[d * 64 + ((tm << 2) ^ s)];
        ull a0 = pack2(a.x, a.x), a1 = pack2(a.y, a.y);
        ull a2 = pack2(a.z, a.z), a3 = pack2(a.w, a.w);
        ffma2(acc[0][0], a0, b.x); ffma2(acc[0][1], a0, b.y);
        ffma2(acc[1][0], a1, b.x); ffma2(acc[1][1], a1, b.y);
        ffma2(acc[2][0], a2, b.x); ffma2(acc[2][1], a2, b.y);
        ffma2(acc[3][0], a3, b.x); ffma2(acc[3][1], a3, b.y);
    }

#pragma unroll
    for (int i = 0; i < 4; i++) {
        float2 p0 = unpack2(acc[i][0]), p1 = unpack2(acc[i][1]);
        const int ng = n0 + (tn << 2) + i;
        const size_t mg = (size_t)(m0 + (tm << 2));
        w[(mg + 0) * 2048 + ng * 8 + h] = 1.f / (1.f + __expf(-p0.x));
        w[(mg + 1) * 2048 + ng * 8 + h] = 1.f / (1.f + __expf(-p0.y));
        w[(mg + 2) * 2048 + ng * 8 + h] = 1.f / (1.f + __expf(-p1.x));
        w[(mg + 3) * 2048 + ng * 8 + h] = 1.f / (1.f + __expf(-p1.y));
    }
}

// ---------------------------------------------------------------------------
// Fused MLP v2: one block per m; 4 n-tiles in-block; j-chunked (64) W2/h1.
//   h1 = relu(A1[m] + sum_h w[n,m,h]*B1[m,h]); h2 = relu(h1@W2+b2);
//   out[n,m] = 0.5*tanh(h2.W3 + b3)
// grid = 512, 256 threads, 50176 B dynamic smem -> 4 blocks/SM
// ---------------------------------------------------------------------------
__global__ __launch_bounds__(256, 4) void fused_main_kernel(
    const float* __restrict__ A1, const float* __restrict__ B1,
    const float* __restrict__ wgt, const float* __restrict__ W2,
    const float* __restrict__ b2, const float* __restrict__ W3,
    const float* __restrict__ b3, float* __restrict__ out)
{
    extern __shared__ float sm[];
    float* W2c = sm;            // 4096 : [jl][k] 64x64 chunk
    float* h1c = sm + 4096;     // 4096 : [jl][n] 64x64 chunk
    float* B1s = sm + 8192;     // 2048 : [j][h]
    float* wS  = sm + 10240;    // 2048 : [n][h], all 256 n of this m
    float* A1s = sm + 12288;    // 256

    const int t = threadIdx.x;
    const int m = blockIdx.x;

    for (int i = t; i < 2048; i += 256) {
        const int h = i >> 8, j = i & 255;
        B1s[(j << 3) + h] = B1[(size_t)m * 2048 + i];
    }
    for (int i = t; i < 2048; i += 256)
        wS[i] = wgt[(size_t)m * 2048 + i];
    A1s[t] = A1[(size_t)m * 256 + t];
    __syncthreads();

    const int n  = t & 63, jg = t >> 6;   // phase-1 mapping (warp-uniform jg)
    const int tn = t >> 4, tk = t & 15;   // phase-2 mapping

    float b2v[4], w3v[4];
#pragma unroll
    for (int j = 0; j < 4; j++) {
        b2v[j] = b2[(tk << 2) + j];
        w3v[j] = W3[(tk << 2) + j];
    }
    const float b3v = b3[0];

    for (int nt = 0; nt < 4; nt++) {
        ull acc2[4][2];
#pragma unroll
        for (int i = 0; i < 4; i++) { acc2[i][0] = 0ull; acc2[i][1] = 0ull; }

        // per-thread attention weights for this n-tile (broadcast LDS)
        float4 wa = *(const float4*)&wS[((nt << 6) + n) << 3];
        float4 wb = *(const float4*)&wS[(((nt << 6) + n) << 3) + 4];
        ull wp0 = pack2(wa.x, wa.y), wp1 = pack2(wa.z, wa.w);
        ull wp2 = pack2(wb.x, wb.y), wp3 = pack2(wb.z, wb.w);

        for (int jc = 0; jc < 4; jc++) {
            // load W2 chunk (coalesced; overlaps with phase-1 compute)
            for (int i = t; i < 1024; i += 256)
                *(float4*)&W2c[i << 2] = *(const float4*)&W2[(jc << 12) + (i << 2)];

            // phase 1: 16 j per thread -> h1c[jl][n]
#pragma unroll 4
            for (int jj = 0; jj < 16; jj++) {
                const int jl = (jg << 4) + jj, j = (jc << 6) + jl;
                ulonglong2 bA = *(const ulonglong2*)&B1s[j << 3];
                ull a = pack2(A1s[j], 0.f);
                ffma2(a, wp0, bA.x); ffma2(a, wp1, bA.y);
                ulonglong2 bB = *(const ulonglong2*)&B1s[(j << 3) + 4];
                ffma2(a, wp2, bB.x); ffma2(a, wp3, bB.y);
                float2 p = unpack2(a);
                h1c[(jl << 6) + n] = fmaxf(p.x + p.y, 0.f);
            }
            __syncthreads();

            // phase 2: acc2 += h1c(64n x 64j) @ W2c(64j x 64k)
#pragma unroll 4
            for (int jl = 0; jl < 64; jl++) {
                float4     a = *(const float4*)&h1c[(jl << 6) + (tn << 2)];
                ulonglong2 b = *(const ulonglong2*)&W2c[(jl << 6) + (tk << 2)];
                ull a0 = pack2(a.x, a.x), a1 = pack2(a.y, a.y);
                ull a2 = pack2(a.z, a.z), a3 = pack2(a.w, a.w);
                ffma2(acc2[0][0], a0, b.x); ffma2(acc2[0][1], a0, b.y);
                ffma2(acc2[1][0], a1, b.x); ffma2(acc2[1][1], a1, b.y);
                ffma2(acc2[2][0], a2, b.x); ffma2(acc2[2][1], a2, b.y);
                ffma2(acc2[3][0], a3, b.x); ffma2(acc2[3][1], a3, b.y);
            }
            __syncthreads();   // protect W2c/h1c before next chunk
        }

        // phase 3: bias+relu, dot W3, reduce across 16 tk-threads, write out
#pragma unroll
        for (int i = 0; i < 4; i++) {
            float2 p0 = unpack2(acc2[i][0]), p1 = unpack2(acc2[i][1]);
            float s = fmaxf(p0.x + b2v[0], 0.f) * w3v[0]
                    + fmaxf(p0.y + b2v[1], 0.f) * w3v[1]
                    + fmaxf(p1.x + b2v[2], 0.f) * w3v[2]
                    + fmaxf(p1.y + b2v[3], 0.f) * w3v[3];
            s += __shfl_xor_sync(0xffffffffu, s, 1);
            s += __shfl_xor_sync(0xffffffffu, s, 2);
            s += __shfl_xor_sync(0xffffffffu, s, 4);
            s += __shfl_xor_sync(0xffffffffu, s, 8);
            if (tk == 0)
                out[(size_t)((nt << 6) + (tn << 2) + i) * 512 + m]
                    = 0.5f * tanhf(s + b3v);
        }
    }
}

// ---------------------------------------------------------------------------
// Scratch (single __device__ global; ~19.2 MB) — allocation-free.
// ---------------------------------------------------------------------------
__device__ float g_scr[4800768];

static const int OFF_Q    = 0;         // 256*768
static const int OFF_IMG  = 196608;    // 512*768
static const int OFF_TGT  = 589824;    // 512*768
static const int OFF_QH   = 983040;    // 256*768
static const int OFF_DK   = 1179648;   // 512*768
static const int OFF_DV   = 1572864;   // 512*768
static const int OFF_VT   = 1966080;   // 512*768
static const int OFF_M1   = 2359296;   // 768*256
static const int OFF_C1B  = 2555904;   // 64*256 (row 0 = c1)
static const int OFF_A1   = 2572288;   // 512*256
static const int OFF_B1   = 2703360;   // 512*8*256
static const int OFF_W    = 3751936;   // 512*256*8

static inline GDesc mk(const float* A, const float* A2, const float* B,
                       const float* bias, float* C, int M, int N, int K,
                       int lda, int ldb, int ldc, float scale)
{
    GDesc g; g.A = A; g.A2 = A2; g.B = B; g.bias = bias; g.C = C;
    g.M = M; g.N = N; g.K = K; g.lda = lda; g.ldb = ldb; g.ldc = ldc;
    g.scale = scale; return g;
}

extern "C" void kernel_launch(void* const* d_in, const int* in_sizes, int n_in,
                              void* d_out, int out_size)
{
    (void)in_sizes; (void)n_in; (void)out_size;
    const float* QE  = (const float*)d_in[0];
    const float* IE  = (const float*)d_in[1];
    const float* TE  = (const float*)d_in[2];
    const float* Wq  = (const float*)d_in[3];
    const float* bq  = (const float*)d_in[4];
    const float* Wi  = (const float*)d_in[5];
    const float* bi  = (const float*)d_in[6];
    const float* Wt  = (const float*)d_in[7];
    const float* bt  = (const float*)d_in[8];
    const float* Wiq = (const float*)d_in[9];
    const float* biq = (const float*)d_in[10];
    const float* Wik = (const float*)d_in[11];
    const float* Wiv = (const float*)d_in[13];
    const float* biv = (const float*)d_in[14];
    const float* Wo  = (const float*)d_in[15];
    const float* bo  = (const float*)d_in[16];
    const float* W1  = (const float*)d_in[17];
    const float* b1  = (const float*)d_in[18];
    const float* W2  = (const float*)d_in[19];
    const float* b2  = (const float*)d_in[20];
    const float* W3  = (const float*)d_in[21];
    const float* b3  = (const float*)d_in[22];
    // note: bik (d_in[12]) cancels in dk = (img - tgt) @ Wik

    float* scr = nullptr;
    cudaGetSymbolAddress((void**)&scr, g_scr);
    float *q   = scr + OFF_Q,   *img = scr + OFF_IMG, *tgt = scr + OFF_TGT;
    float *qh  = scr + OFF_QH,  *dk  = scr + OFF_DK,  *dv  = scr + OFF_DV;
    float *vt  = scr + OFF_VT,  *M1  = scr + OFF_M1,  *c1b = scr + OFF_C1B;
    float *A1  = scr + OFF_A1,  *B1  = scr + OFF_B1,  *w   = scr + OFF_W;

    const float scale = 1.0f / sqrtf(96.0f);

    // Stage 1: input projections, M1 = Wo@W1, c1 = bo@W1 + b1 (lda=0 bcast)
    {
        GBatch b;
        b.d[0] = mk(QE, nullptr, Wq, bq,      q,   256, 768, 768, 768, 768, 768, 1.f);
        b.d[1] = mk(IE, nullptr, Wi, bi,      img, 512, 768, 768, 768, 768, 768, 1.f);
        b.d[2] = mk(TE, nullptr, Wt, bt,      tgt, 512, 768, 768, 768, 768, 768, 1.f);
        b.d[3] = mk(Wo, nullptr, W1, nullptr, M1,  768, 256, 768, 768, 256, 256, 1.f);
        b.d[4] = mk(bo, nullptr, W1, b1,      c1b, 64,  256, 768, 0,   256, 256, 1.f);
        sgemm64b<<<dim3(12, 12, 5), 256>>>(b);
    }

    // Stage 2: MHA in-projections (k/v biases cancel in the img-tgt diffs)
    {
        GBatch b;
        b.d[0] = mk(q,   nullptr, Wiq, biq,     qh, 256, 768, 768, 768, 768, 768, scale);
        b.d[1] = mk(img, tgt,     Wik, nullptr, dk, 512, 768, 768, 768, 768, 768, 1.f);
        b.d[2] = mk(img, tgt,     Wiv, nullptr, dv, 512, 768, 768, 768, 768, 768, 1.f);
        b.d[3] = mk(tgt, nullptr, Wiv, biv,     vt, 512, 768, 768, 768, 768, 768, 1.f);
        sgemm64b<<<dim3(12, 8, 4), 256>>>(b);
    }

    // Stage 3: A1 = vt@M1 + c1 ; B1[m][h] = dv[m,h*96:]@M1[h*96:,:]
    {
        GBatch b;
        b.d[0] = mk(vt, nullptr, M1, c1b, A1, 512, 256, 768, 768, 256, 256, 1.f);
        for (int h = 0; h < 8; h++)
            b.d[1 + h] = mk(dv + h * 96, nullptr, M1 + h * 96 * 256, nullptr,
                            B1 + h * 256, 512, 256, 96, 768, 256, 2048, 1.f);
        sgemm64b<<<dim3(4, 8, 9), 256>>>(b);
    }

    // attention weights (64x64 tiles per head)
    logits_w_kernel<<<dim3(8, 4, 8), 256>>>(qh, dk, w);

    // fused MLP + output (one block per m; 50176 B smem -> 4 blocks/SM)
    cudaFuncSetAttribute(fused_main_kernel,
                         cudaFuncAttributeMaxDynamicSharedMemorySize, 50176);
    fused_main_kernel<<<512, 256, 50176>>>(A1, B1, w, W2, b2, W3, b3,
                                           (float*)d_out);
}